// round 1
// baseline (speedup 1.0000x reference)
#include <cuda_runtime.h>
#include <math.h>
#include <stdint.h>

// Problem constants
#define BB 32
#define TT 2048
#define EE 1024
#define MTOT (BB * TT)   // 65536

// Scratch (device globals — no allocation in kernel_launch)
__device__ float g_ht[(size_t)MTOT * EE];   // 256 MB: tanh(enc@W + b)
__device__ float g_scores[MTOT];
__device__ float g_at[MTOT];

// ---------------------------------------------------------------------------
// Kernel 1: SGEMM (M=65536, N=1024, K=1024) with fused bias + tanh epilogue.
// Classic 128x128 block tile, BK=8, 256 threads, 8x8 per-thread microtile,
// double-buffered shared memory.
// ---------------------------------------------------------------------------
__global__ void __launch_bounds__(256, 2) gemm_tanh_kernel(
    const float* __restrict__ A,      // enc, (M, K) row-major
    const float* __restrict__ Wm,     // W,   (K, N) row-major
    const float* __restrict__ bias)   // b,   (N)
{
    const int K = EE;
    const int N = EE;

    __shared__ float As[2][8][128];   // transposed: As[k][m]
    __shared__ float Bs[2][8][128];   // Bs[k][n]

    const int tid = threadIdx.x;
    const int bx = blockIdx.x;        // N tile index (0..7)
    const int by = blockIdx.y;        // M tile index (0..511)

    // Global load mapping
    const int a_row = tid >> 1;            // 0..127
    const int a_kc  = (tid & 1) << 2;      // 0 or 4
    const int b_row = tid >> 5;            // 0..7
    const int b_col = (tid & 31) << 2;     // 0..124

    const float* Ap = A + ((size_t)by * 128 + a_row) * (size_t)K + a_kc;
    const float* Bp = Wm + (size_t)b_row * N + bx * 128 + b_col;

    // Preload tile 0
    float4 av = *(const float4*)Ap;
    float4 bv = *(const float4*)Bp;
    As[0][a_kc + 0][a_row] = av.x;
    As[0][a_kc + 1][a_row] = av.y;
    As[0][a_kc + 2][a_row] = av.z;
    As[0][a_kc + 3][a_row] = av.w;
    *(float4*)&Bs[0][b_row][b_col] = bv;
    __syncthreads();

    const int tx = tid & 15;   // N direction (0..15)
    const int ty = tid >> 4;   // M direction (0..15)

    float acc[8][8];
#pragma unroll
    for (int i = 0; i < 8; i++)
#pragma unroll
        for (int j = 0; j < 8; j++) acc[i][j] = 0.0f;

    const int nk = K / 8;   // 128
    for (int kb = 0; kb < nk; kb++) {
        const int cur = kb & 1;
        const int nxt = cur ^ 1;

        float4 av2, bv2;
        if (kb + 1 < nk) {
            av2 = *(const float4*)(Ap + (kb + 1) * 8);
            bv2 = *(const float4*)(Bp + (size_t)(kb + 1) * 8 * N);
        }

#pragma unroll
        for (int k = 0; k < 8; k++) {
            float4 ra0 = *(const float4*)&As[cur][k][ty * 8];
            float4 ra1 = *(const float4*)&As[cur][k][ty * 8 + 4];
            float4 rb0 = *(const float4*)&Bs[cur][k][tx * 8];
            float4 rb1 = *(const float4*)&Bs[cur][k][tx * 8 + 4];
            float ra[8] = {ra0.x, ra0.y, ra0.z, ra0.w, ra1.x, ra1.y, ra1.z, ra1.w};
            float rb[8] = {rb0.x, rb0.y, rb0.z, rb0.w, rb1.x, rb1.y, rb1.z, rb1.w};
#pragma unroll
            for (int i = 0; i < 8; i++)
#pragma unroll
                for (int j = 0; j < 8; j++)
                    acc[i][j] += ra[i] * rb[j];
        }

        if (kb + 1 < nk) {
            As[nxt][a_kc + 0][a_row] = av2.x;
            As[nxt][a_kc + 1][a_row] = av2.y;
            As[nxt][a_kc + 2][a_row] = av2.z;
            As[nxt][a_kc + 3][a_row] = av2.w;
            *(float4*)&Bs[nxt][b_row][b_col] = bv2;
        }
        __syncthreads();
    }

    // Epilogue: tanh(acc + bias), write ht
    const size_t row0 = (size_t)by * 128 + ty * 8;
    const int col0 = bx * 128 + tx * 8;
    float bcache[8];
#pragma unroll
    for (int j = 0; j < 8; j++) bcache[j] = bias[col0 + j];

#pragma unroll
    for (int i = 0; i < 8; i++) {
        float4 o0, o1;
        o0.x = tanhf(acc[i][0] + bcache[0]);
        o0.y = tanhf(acc[i][1] + bcache[1]);
        o0.z = tanhf(acc[i][2] + bcache[2]);
        o0.w = tanhf(acc[i][3] + bcache[3]);
        o1.x = tanhf(acc[i][4] + bcache[4]);
        o1.y = tanhf(acc[i][5] + bcache[5]);
        o1.z = tanhf(acc[i][6] + bcache[6]);
        o1.w = tanhf(acc[i][7] + bcache[7]);
        float* hp = g_ht + (row0 + i) * (size_t)EE + col0;
        *(float4*)hp = o0;
        *(float4*)(hp + 4) = o1;
    }
}

// ---------------------------------------------------------------------------
// Kernel 2: scores[b][t] = dot(ctx[b], ht[b][t]). One warp per timestep.
// grid: (TT/8, BB), 256 threads (8 warps)
// ---------------------------------------------------------------------------
__global__ void __launch_bounds__(256) scores_kernel(const float* __restrict__ ctx)
{
    __shared__ float cs[EE];
    const int b = blockIdx.y;

    for (int i = threadIdx.x; i < EE; i += 256)
        cs[i] = ctx[b * EE + i];
    __syncthreads();

    const int warp = threadIdx.x >> 5;
    const int lane = threadIdx.x & 31;
    const int t = blockIdx.x * 8 + warp;

    const float4* hp = (const float4*)(g_ht + ((size_t)(b * TT + t)) * EE);
    float acc = 0.0f;
#pragma unroll
    for (int i = 0; i < EE / 4; i += 32) {
        float4 h = hp[i + lane];
        const int e = (i + lane) * 4;
        acc += h.x * cs[e] + h.y * cs[e + 1] + h.z * cs[e + 2] + h.w * cs[e + 3];
    }
#pragma unroll
    for (int o = 16; o > 0; o >>= 1)
        acc += __shfl_down_sync(0xffffffffu, acc, o);
    if (lane == 0)
        g_scores[b * TT + t] = acc;
}

// ---------------------------------------------------------------------------
// Kernel 3: softmax over T per batch. grid: BB blocks, 256 threads (8 elems each)
// ---------------------------------------------------------------------------
__global__ void __launch_bounds__(256) softmax_kernel()
{
    __shared__ float red[256];
    const int b = blockIdx.x;
    const int tid = threadIdx.x;

    float v[8];
    float m = -1e30f;
#pragma unroll
    for (int i = 0; i < 8; i++) {
        v[i] = g_scores[b * TT + tid + i * 256];
        m = fmaxf(m, v[i]);
    }
    red[tid] = m;
    __syncthreads();
#pragma unroll
    for (int s = 128; s > 0; s >>= 1) {
        if (tid < s) red[tid] = fmaxf(red[tid], red[tid + s]);
        __syncthreads();
    }
    const float mx = red[0];
    __syncthreads();

    float sum = 0.0f;
#pragma unroll
    for (int i = 0; i < 8; i++) {
        v[i] = expf(v[i] - mx);
        sum += v[i];
    }
    red[tid] = sum;
    __syncthreads();
#pragma unroll
    for (int s = 128; s > 0; s >>= 1) {
        if (tid < s) red[tid] += red[tid + s];
        __syncthreads();
    }
    const float inv = 1.0f / red[0];
#pragma unroll
    for (int i = 0; i < 8; i++)
        g_at[b * TT + tid + i * 256] = v[i] * inv;
}

// ---------------------------------------------------------------------------
// Kernel 4: out[b][e] = sum_t at[b][t] * ht[b][t][e]
// grid: (EE/256, TT/256, BB), 256 threads. Partial sums via atomicAdd.
// ---------------------------------------------------------------------------
__global__ void __launch_bounds__(256) pool_kernel(float* __restrict__ out)
{
    __shared__ float ats[256];
    const int b = blockIdx.z;
    const int e = blockIdx.x * 256 + threadIdx.x;
    const int t0 = blockIdx.y * 256;

    ats[threadIdx.x] = g_at[b * TT + t0 + threadIdx.x];
    __syncthreads();

    const float* hp = g_ht + ((size_t)(b * TT + t0)) * EE + e;
    float acc = 0.0f;
#pragma unroll 8
    for (int i = 0; i < 256; i++)
        acc += ats[i] * hp[(size_t)i * EE];

    atomicAdd(&out[b * EE + e], acc);
}

// ---------------------------------------------------------------------------
// Launch
// ---------------------------------------------------------------------------
extern "C" void kernel_launch(void* const* d_in, const int* in_sizes, int n_in,
                              void* d_out, int out_size)
{
    const float* enc  = (const float*)d_in[0];   // (B, T, E)
    const float* ctx  = (const float*)d_in[1];   // (B, E)
    const float* Wm   = (const float*)d_in[2];   // (E, E)
    const float* bias = (const float*)d_in[3];   // (1, E)
    float* out = (float*)d_out;                  // (B, E)

    cudaMemsetAsync(out, 0, sizeof(float) * BB * EE);

    gemm_tanh_kernel<<<dim3(EE / 128, MTOT / 128), 256>>>(enc, Wm, bias);
    scores_kernel<<<dim3(TT / 8, BB), 256>>>(ctx);
    softmax_kernel<<<BB, 256>>>();
    pool_kernel<<<dim3(EE / 256, TT / 256, BB), 256>>>(out);
}

// round 3
// speedup vs baseline: 2.7452x; 2.7452x over previous
#include <cuda_runtime.h>
#include <cuda_bf16.h>
#include <math.h>
#include <stdint.h>

#define BB 32
#define TT 2048
#define EE 1024
#define MTOT (BB * TT)   // 65536

// ---------------- device scratch ----------------
__device__ float g_ht[(size_t)MTOT * EE];                 // 256 MB
__device__ float g_scores[MTOT];
__device__ float g_at[MTOT];
__device__ __nv_bfloat16 g_Ahi[(size_t)MTOT * EE];        // 128 MB
__device__ __nv_bfloat16 g_Alo[(size_t)MTOT * EE];        // 128 MB
__device__ __nv_bfloat16 g_Bhi[(size_t)EE * EE];          // Wt hi (N,K)
__device__ __nv_bfloat16 g_Blo[(size_t)EE * EE];          // Wt lo (N,K)

// ---------------- helpers ----------------
__device__ __forceinline__ uint32_t smem_u32(const void* p) {
    uint32_t a;
    asm("{ .reg .u64 t; cvta.to.shared.u64 t, %1; cvt.u32.u64 %0, t; }"
        : "=r"(a) : "l"(p));
    return a;
}

__device__ __forceinline__ void cpasync16(uint32_t smem_dst, const void* gptr) {
    asm volatile("cp.async.cg.shared.global [%0], [%1], 16;"
                 :: "r"(smem_dst), "l"(gptr) : "memory");
}

__device__ __forceinline__ void ldsm4(uint32_t* r, uint32_t addr) {
    asm volatile("ldmatrix.sync.aligned.m8n8.x4.shared.b16 {%0,%1,%2,%3}, [%4];"
                 : "=r"(r[0]), "=r"(r[1]), "=r"(r[2]), "=r"(r[3]) : "r"(addr));
}

__device__ __forceinline__ void mma16816(float* c, const uint32_t* a, const uint32_t* b) {
    asm volatile("mma.sync.aligned.m16n8k16.row.col.f32.bf16.bf16.f32 "
                 "{%0,%1,%2,%3}, {%4,%5,%6,%7}, {%8,%9}, {%0,%1,%2,%3};"
                 : "+f"(c[0]), "+f"(c[1]), "+f"(c[2]), "+f"(c[3])
                 : "r"(a[0]), "r"(a[1]), "r"(a[2]), "r"(a[3]),
                   "r"(b[0]), "r"(b[1]));
}

// ---------------- GEMM config ----------------
#define MT 256
#define NT 128
#define BK 64                         // bf16 elems per chunk (128 B rows)
#define NCHUNK (EE / BK)              // 16
#define OFF_AHI 0
#define OFF_ALO (MT * BK * 2)                       // 32768
#define OFF_BHI (2 * MT * BK * 2)                   // 65536
#define OFF_BLO (2 * MT * BK * 2 + NT * BK * 2)     // 81920
#define STAGE_BYTES (2 * (MT + NT) * BK * 2)        // 98304
#define DSM_BYTES (2 * STAGE_BYTES)                 // 196608

// ---------------- prepass: split enc into bf16 hi/lo ----------------
__global__ void __launch_bounds__(256) split_enc_kernel(const float* __restrict__ A)
{
    size_t i = ((size_t)blockIdx.x * 256 + threadIdx.x) * 4;
    float4 v = *(const float4*)(A + i);
    __nv_bfloat16 h0 = __float2bfloat16(v.x);
    __nv_bfloat16 h1 = __float2bfloat16(v.y);
    __nv_bfloat16 h2 = __float2bfloat16(v.z);
    __nv_bfloat16 h3 = __float2bfloat16(v.w);
    __nv_bfloat16 l0 = __float2bfloat16(v.x - __bfloat162float(h0));
    __nv_bfloat16 l1 = __float2bfloat16(v.y - __bfloat162float(h1));
    __nv_bfloat16 l2 = __float2bfloat16(v.z - __bfloat162float(h2));
    __nv_bfloat16 l3 = __float2bfloat16(v.w - __bfloat162float(h3));
    __nv_bfloat162 hp0 = __halves2bfloat162(h0, h1);
    __nv_bfloat162 hp1 = __halves2bfloat162(h2, h3);
    __nv_bfloat162 lp0 = __halves2bfloat162(l0, l1);
    __nv_bfloat162 lp1 = __halves2bfloat162(l2, l3);
    *(uint2*)(g_Ahi + i) = make_uint2(*(uint32_t*)&hp0, *(uint32_t*)&hp1);
    *(uint2*)(g_Alo + i) = make_uint2(*(uint32_t*)&lp0, *(uint32_t*)&lp1);
}

// ---------------- prepass: transpose + split W -> Wt[n][k] hi/lo ----------------
__global__ void __launch_bounds__(256) splitW_kernel(const float* __restrict__ W)
{
    __shared__ float tile[32][33];
    int n0 = blockIdx.x * 32, k0 = blockIdx.y * 32;
    int tx = threadIdx.x & 31, ty = threadIdx.x >> 5;  // 32 x 8
#pragma unroll
    for (int r = 0; r < 4; r++)
        tile[ty + 8 * r][tx] = W[(size_t)(k0 + ty + 8 * r) * EE + n0 + tx];
    __syncthreads();
#pragma unroll
    for (int r = 0; r < 4; r++) {
        int ny = ty + 8 * r;
        float v = tile[tx][ny];
        __nv_bfloat16 h = __float2bfloat16(v);
        __nv_bfloat16 l = __float2bfloat16(v - __bfloat162float(h));
        size_t o = (size_t)(n0 + ny) * EE + k0 + tx;
        g_Bhi[o] = h;
        g_Blo[o] = l;
    }
}

// ---------------- HMMA GEMM + bias + tanh ----------------
__device__ __forceinline__ void load_chunk(int c, uint32_t sm0, size_t m0, int n0, int tid)
{
    uint32_t sb = sm0 + (uint32_t)(c & 1) * STAGE_BYTES;
    int k0 = c * BK;
    const __nv_bfloat16* Ahi = g_Ahi + m0 * EE + k0;
    const __nv_bfloat16* Alo = g_Alo + m0 * EE + k0;
    const __nv_bfloat16* Bhi = g_Bhi + (size_t)n0 * EE + k0;
    const __nv_bfloat16* Blo = g_Blo + (size_t)n0 * EE + k0;
#pragma unroll
    for (int i = 0; i < 8; i++) {           // A: 256 rows x 8 chunks of 16B
        int idx = tid + i * 256;
        int row = idx >> 3, j = idx & 7;
        uint32_t d = sb + (uint32_t)(row * 128 + ((j ^ (row & 7)) << 4));
        const size_t go = (size_t)row * EE + j * 8;
        cpasync16(d + OFF_AHI, Ahi + go);
        cpasync16(d + OFF_ALO, Alo + go);
    }
#pragma unroll
    for (int i = 0; i < 4; i++) {           // B: 128 rows x 8 chunks of 16B
        int idx = tid + i * 256;
        int row = idx >> 3, j = idx & 7;
        uint32_t d = sb + (uint32_t)(row * 128 + ((j ^ (row & 7)) << 4));
        const size_t go = (size_t)row * EE + j * 8;
        cpasync16(d + OFF_BHI, Bhi + go);
        cpasync16(d + OFF_BLO, Blo + go);
    }
    asm volatile("cp.async.commit_group;" ::: "memory");
}

// fragment smem addresses (XOR-16B swizzled, 128 B rows)
__device__ __forceinline__ uint32_t a_frag_addr(uint32_t base, int row0, int t, int lane) {
    int r = row0 + (lane & 15);
    int j = t * 2 + (lane >> 4);
    return base + (uint32_t)(r * 128 + ((j ^ (r & 7)) << 4));
}
__device__ __forceinline__ uint32_t b_frag_addr(uint32_t base, int n0, int t, int lane) {
    int r = n0 + (lane & 7) + ((lane & 16) >> 1);
    int j = t * 2 + ((lane >> 3) & 1);
    return base + (uint32_t)(r * 128 + ((j ^ (r & 7)) << 4));
}

__global__ void __launch_bounds__(256, 1) gemm_hmma_kernel(const float* __restrict__ bias)
{
    extern __shared__ __align__(1024) char dsm_raw[];
    uint32_t sm0 = smem_u32(dsm_raw);

    __shared__ float s_bias[NT];

    const int tid = threadIdx.x;
    const int wid = tid >> 5, lane = tid & 31;
    const int warp_m = wid >> 1;            // 0..3 (64-row slabs)
    const int warp_n = wid & 1;             // 0..1 (64-col slabs)
    const int n0c = blockIdx.x * NT;
    const size_t m0 = (size_t)blockIdx.y * MT;

    for (int i = tid; i < NT; i += 256) s_bias[i] = bias[n0c + i];

    float acc[4][8][4];
#pragma unroll
    for (int mi = 0; mi < 4; mi++)
#pragma unroll
        for (int ni = 0; ni < 8; ni++)
#pragma unroll
            for (int e = 0; e < 4; e++) acc[mi][ni][e] = 0.0f;

    load_chunk(0, sm0, m0, n0c, tid);
    load_chunk(1, sm0, m0, n0c, tid);

    for (int c = 0; c < NCHUNK; c++) {
        if (c == NCHUNK - 1)
            asm volatile("cp.async.wait_group 0;" ::: "memory");
        else
            asm volatile("cp.async.wait_group 1;" ::: "memory");
        __syncthreads();

        const uint32_t sb = sm0 + (uint32_t)(c & 1) * STAGE_BYTES;
        const uint32_t sAhi = sb + OFF_AHI;
        const uint32_t sAlo = sb + OFF_ALO;
        const uint32_t sBhi = sb + OFF_BHI;
        const uint32_t sBlo = sb + OFF_BLO;

#pragma unroll
        for (int t = 0; t < 4; t++) {       // 4 k16 steps per BK=64
            uint32_t af[4][4], bh[4][4], bl[4][4];
#pragma unroll
            for (int mi = 0; mi < 4; mi++)
                ldsm4(af[mi], a_frag_addr(sAhi, warp_m * 64 + mi * 16, t, lane));
#pragma unroll
            for (int np = 0; np < 4; np++)
                ldsm4(bh[np], b_frag_addr(sBhi, warp_n * 64 + np * 16, t, lane));
#pragma unroll
            for (int np = 0; np < 4; np++)
                ldsm4(bl[np], b_frag_addr(sBlo, warp_n * 64 + np * 16, t, lane));

            // Ahi*Bhi + Ahi*Blo
#pragma unroll
            for (int mi = 0; mi < 4; mi++)
#pragma unroll
                for (int ni = 0; ni < 8; ni++) {
                    mma16816(acc[mi][ni], af[mi], &bh[ni >> 1][(ni & 1) * 2]);
                    mma16816(acc[mi][ni], af[mi], &bl[ni >> 1][(ni & 1) * 2]);
                }
            // Alo*Bhi (reuse af regs)
#pragma unroll
            for (int mi = 0; mi < 4; mi++)
                ldsm4(af[mi], a_frag_addr(sAlo, warp_m * 64 + mi * 16, t, lane));
#pragma unroll
            for (int mi = 0; mi < 4; mi++)
#pragma unroll
                for (int ni = 0; ni < 8; ni++)
                    mma16816(acc[mi][ni], af[mi], &bh[ni >> 1][(ni & 1) * 2]);
        }

        __syncthreads();
        if (c + 2 < NCHUNK) load_chunk(c + 2, sm0, m0, n0c, tid);
    }

    // epilogue: bias + tanh, write ht
    const int lr = lane >> 2;               // 0..7
    const int lc = (lane & 3) * 2;
#pragma unroll
    for (int mi = 0; mi < 4; mi++) {
        const size_t row0 = m0 + (size_t)(warp_m * 64 + mi * 16 + lr);
#pragma unroll
        for (int ni = 0; ni < 8; ni++) {
            const int col = warp_n * 64 + ni * 8 + lc;
            const float b0 = s_bias[col], b1 = s_bias[col + 1];
            float2 v0, v1;
            v0.x = tanhf(acc[mi][ni][0] + b0);
            v0.y = tanhf(acc[mi][ni][1] + b1);
            v1.x = tanhf(acc[mi][ni][2] + b0);
            v1.y = tanhf(acc[mi][ni][3] + b1);
            *(float2*)(g_ht + row0 * EE + n0c + col) = v0;
            *(float2*)(g_ht + (row0 + 8) * EE + n0c + col) = v1;
        }
    }
}

// ---------------- scores / softmax / pool ----------------
__global__ void __launch_bounds__(256) scores_kernel(const float* __restrict__ ctx)
{
    __shared__ float cs[EE];
    const int b = blockIdx.y;
    for (int i = threadIdx.x; i < EE; i += 256)
        cs[i] = ctx[b * EE + i];
    __syncthreads();

    const int warp = threadIdx.x >> 5;
    const int lane = threadIdx.x & 31;
    const int t = blockIdx.x * 8 + warp;

    const float4* hp = (const float4*)(g_ht + ((size_t)(b * TT + t)) * EE);
    float acc = 0.0f;
#pragma unroll
    for (int i = 0; i < EE / 4; i += 32) {
        float4 h = hp[i + lane];
        const int e = (i + lane) * 4;
        acc += h.x * cs[e] + h.y * cs[e + 1] + h.z * cs[e + 2] + h.w * cs[e + 3];
    }
#pragma unroll
    for (int o = 16; o > 0; o >>= 1)
        acc += __shfl_down_sync(0xffffffffu, acc, o);
    if (lane == 0)
        g_scores[b * TT + t] = acc;
}

__global__ void __launch_bounds__(256) softmax_kernel()
{
    __shared__ float red[256];
    const int b = blockIdx.x;
    const int tid = threadIdx.x;

    float v[8];
    float m = -1e30f;
#pragma unroll
    for (int i = 0; i < 8; i++) {
        v[i] = g_scores[b * TT + tid + i * 256];
        m = fmaxf(m, v[i]);
    }
    red[tid] = m;
    __syncthreads();
#pragma unroll
    for (int s = 128; s > 0; s >>= 1) {
        if (tid < s) red[tid] = fmaxf(red[tid], red[tid + s]);
        __syncthreads();
    }
    const float mx = red[0];
    __syncthreads();

    float sum = 0.0f;
#pragma unroll
    for (int i = 0; i < 8; i++) {
        v[i] = expf(v[i] - mx);
        sum += v[i];
    }
    red[tid] = sum;
    __syncthreads();
#pragma unroll
    for (int s = 128; s > 0; s >>= 1) {
        if (tid < s) red[tid] += red[tid + s];
        __syncthreads();
    }
    const float inv = 1.0f / red[0];
#pragma unroll
    for (int i = 0; i < 8; i++)
        g_at[b * TT + tid + i * 256] = v[i] * inv;
}

__global__ void __launch_bounds__(256) pool_kernel(float* __restrict__ out)
{
    __shared__ float ats[256];
    const int b = blockIdx.z;
    const int e = blockIdx.x * 256 + threadIdx.x;
    const int t0 = blockIdx.y * 256;

    ats[threadIdx.x] = g_at[b * TT + t0 + threadIdx.x];
    __syncthreads();

    const float* hp = g_ht + ((size_t)(b * TT + t0)) * EE + e;
    float acc = 0.0f;
#pragma unroll 8
    for (int i = 0; i < 256; i++)
        acc += ats[i] * hp[(size_t)i * EE];

    atomicAdd(&out[b * EE + e], acc);
}

// ---------------- launch ----------------
extern "C" void kernel_launch(void* const* d_in, const int* in_sizes, int n_in,
                              void* d_out, int out_size)
{
    const float* enc  = (const float*)d_in[0];   // (B, T, E)
    const float* ctx  = (const float*)d_in[1];   // (B, E)
    const float* Wm   = (const float*)d_in[2];   // (E, E)
    const float* bias = (const float*)d_in[3];   // (1, E)
    float* out = (float*)d_out;                  // (B, E)

    cudaFuncSetAttribute(gemm_hmma_kernel,
                         cudaFuncAttributeMaxDynamicSharedMemorySize, DSM_BYTES);

    cudaMemsetAsync(out, 0, sizeof(float) * BB * EE);

    split_enc_kernel<<<(size_t)MTOT * EE / 1024, 256>>>(enc);
    splitW_kernel<<<dim3(EE / 32, EE / 32), 256>>>(Wm);
    gemm_hmma_kernel<<<dim3(EE / NT, MTOT / MT), 256, DSM_BYTES>>>(bias);
    scores_kernel<<<dim3(TT / 8, BB), 256>>>(ctx);
    softmax_kernel<<<BB, 256>>>();
    pool_kernel<<<dim3(EE / 256, TT / 256, BB), 256>>>(out);
}